// round 14
// baseline (speedup 1.0000x reference)
#include <cuda_runtime.h>
#include <cstdint>

#define S 256
#define E 64
#define KNB 20
#define NTHREADS 256
#define NWARPS 8
#define XSTRIDE 260   // padded row stride for Xs (16B-aligned, breaks STS conflicts)

// logit(0.1): sigmoid(acc) > 0.1  <=>  acc > LOGIT_THR
#define LOGIT_THR (-2.1972245773362196f)

// shared memory layout (in floats)
#define XS_OFF   0        // 64*260 = 16640: Xs[e][j], e-major stride 260 (reused as key dump)
#define SROW_OFF 16640    // 8192: per-warp 4 normalized-sims row buffers (reused as wtop)
#define TW_OFF   24832    // 256
#define IW_OFF   25088    // 256
#define RED_OFF  25344    // 64 (8B aligned) reduction scratch
#define WT_OFF   25408    // 96: a1,a2,a3,b1,w2,b2
#define SMEM_FLOATS 25504
#define SMEM_BYTES (SMEM_FLOATS * 4)

typedef unsigned long long ull;

// order-preserving uint32 of a float (handles negatives)
__device__ __forceinline__ unsigned f2ord(float f) {
    unsigned u = __float_as_uint(f);
    return u ^ ((u & 0x80000000u) ? 0xffffffffu : 0x80000000u);
}

// value (float) encoded in the high word of a key; -big for empty key
__device__ __forceinline__ float keyval(ull g) {
    if (g == 0ull) return -3.0e38f;
    unsigned u = (unsigned)(g >> 32);
    unsigned bits = (u & 0x80000000u) ? (u ^ 0x80000000u) : ~u;   // inverse f2ord
    return __uint_as_float(bits);
}

__device__ __forceinline__ ull wmax64(ull v) {
    #pragma unroll
    for (int o = 16; o > 0; o >>= 1) {
        ull t = __shfl_xor_sync(0xffffffffu, v, o);
        v = (t > v) ? t : v;
    }
    return v;
}

__global__ __launch_bounds__(NTHREADS, 2)
void ugc_kernel(const float* __restrict__ item,
                const float* __restrict__ tsg,
                const float* __restrict__ iwg,
                const float* __restrict__ gW1,
                const float* __restrict__ gb1,
                const float* __restrict__ gW2,
                const float* __restrict__ gb2,
                float* __restrict__ out)
{
    extern __shared__ float sm[];
    float* Xs    = sm + XS_OFF;
    float* srow  = sm + SROW_OFF;
    float* s_tw  = sm + TW_OFF;
    float* s_iw  = sm + IW_OFF;
    float* s_red = sm + RED_OFF;
    float* s_wt  = sm + WT_OFF;

    const int b   = blockIdx.x;
    const int tid = threadIdx.x;
    const int w   = tid >> 5;
    const int l   = tid & 31;

    // ---- stage MLP weights into smem (tiny) ----
    if (tid < 16) {
        s_wt[tid]      = gW1[tid];        // a1
        s_wt[16 + tid] = gW1[16 + tid];   // a2
        s_wt[32 + tid] = gW1[32 + tid];   // a3
        s_wt[48 + tid] = gb1[tid];        // b1
        s_wt[64 + tid] = gW2[tid];        // w2
    }
    if (tid == 0) s_wt[80] = gb2[0];

    // ---- timestamps max -> temporal weights; interaction weights ----
    const float tsv = tsg[b * S + tid];
    float v = tsv;
    #pragma unroll
    for (int o = 16; o > 0; o >>= 1) v = fmaxf(v, __shfl_xor_sync(0xffffffffu, v, o));
    if (l == 0) s_red[w] = v;
    __syncthreads();
    float tmax = s_red[0];
    #pragma unroll
    for (int r = 1; r < NWARPS; r++) tmax = fmaxf(tmax, s_red[r]);
    const float LN095 = -0.05129329438755058f;      // ln(0.95)
    s_tw[tid] = __expf(LN095 * (tmax - tsv));       // 0.95^(tmax - ts)
    s_iw[tid] = iwg[b * S + tid];

    // ---- stage X transposed into SMEM via coalesced 4x4 block transpose ----
    // Xs[e*XSTRIDE + j] = X[j][e]
    {
        const float* Xg = item + (size_t)b * (S * E);
        #pragma unroll
        for (int it = 0; it < 4; it++) {
            int blk = it * NTHREADS + tid;      // 0..1023 blocks of 4x4
            int eb  = blk & 15;                 // e-block (16 per row group)
            int jb  = blk >> 4;                 // j-block (64)
            float4 r0 = *(const float4*)(Xg + (4 * jb + 0) * E + 4 * eb);
            float4 r1 = *(const float4*)(Xg + (4 * jb + 1) * E + 4 * eb);
            float4 r2 = *(const float4*)(Xg + (4 * jb + 2) * E + 4 * eb);
            float4 r3 = *(const float4*)(Xg + (4 * jb + 3) * E + 4 * eb);
            *(float4*)(Xs + (4 * eb + 0) * XSTRIDE + 4 * jb) = make_float4(r0.x, r1.x, r2.x, r3.x);
            *(float4*)(Xs + (4 * eb + 1) * XSTRIDE + 4 * jb) = make_float4(r0.y, r1.y, r2.y, r3.y);
            *(float4*)(Xs + (4 * eb + 2) * XSTRIDE + 4 * jb) = make_float4(r0.z, r1.z, r2.z, r3.z);
            *(float4*)(Xs + (4 * eb + 3) * XSTRIDE + 4 * jb) = make_float4(r0.w, r1.w, r2.w, r3.w);
        }
    }
    __syncthreads();

    // ---- per-thread top-K (sorted ascending register list of packed keys) ----
    ull best[KNB];
    #pragma unroll
    for (int n = 0; n < KNB; n++) best[n] = 0ull;
    ull  warpThr = 0ull;        // warp-wide valid discard bound
    ull  gate    = 0ull;        // max(warpThr, best[0])
    float gateF  = LOGIT_THR;   // single-compare gate (subsumes edge threshold)

    // ---- main loop: 8 passes; warp owns adjacent row block {4m..4m+3},
    //      m = 8*pass + (pass odd ? 7-w : w)  -> exactly 4080 MLP points per warp ----
    for (int pass = 0; pass < 8; pass++) {
        const int m  = 8 * pass + ((pass & 1) ? (7 - w) : w);   // 0..63
        const int rbase0 = 4 * m;

        // 4x256 gram block: 32 accumulators; ONE LDS.128 broadcast serves 4 rows
        float a00=0,a01=0,a02=0,a03=0,a04=0,a05=0,a06=0,a07=0;
        float a10=0,a11=0,a12=0,a13=0,a14=0,a15=0,a16=0,a17=0;
        float a20=0,a21=0,a22=0,a23=0,a24=0,a25=0,a26=0,a27=0;
        float a30=0,a31=0,a32=0,a33=0,a34=0,a35=0,a36=0,a37=0;

        const float* bp = Xs;
        #pragma unroll 16
        for (int e = 0; e < E; e++) {
            float4 A  = *(const float4*)(bp + 4 * l);
            float4 Bv = *(const float4*)(bp + 128 + 4 * l);
            float4 X4 = *(const float4*)(bp + rbase0);      // broadcast: rows 4m..4m+3
            float x0 = X4.x, x1 = X4.y, x2 = X4.z, x3 = X4.w;
            a00=fmaf(x0,A.x,a00); a01=fmaf(x0,A.y,a01); a02=fmaf(x0,A.z,a02); a03=fmaf(x0,A.w,a03);
            a04=fmaf(x0,Bv.x,a04);a05=fmaf(x0,Bv.y,a05);a06=fmaf(x0,Bv.z,a06);a07=fmaf(x0,Bv.w,a07);
            a10=fmaf(x1,A.x,a10); a11=fmaf(x1,A.y,a11); a12=fmaf(x1,A.z,a12); a13=fmaf(x1,A.w,a13);
            a14=fmaf(x1,Bv.x,a14);a15=fmaf(x1,Bv.y,a15);a16=fmaf(x1,Bv.z,a16);a17=fmaf(x1,Bv.w,a17);
            a20=fmaf(x2,A.x,a20); a21=fmaf(x2,A.y,a21); a22=fmaf(x2,A.z,a22); a23=fmaf(x2,A.w,a23);
            a24=fmaf(x2,Bv.x,a24);a25=fmaf(x2,Bv.y,a25);a26=fmaf(x2,Bv.z,a26);a27=fmaf(x2,Bv.w,a27);
            a30=fmaf(x3,A.x,a30); a31=fmaf(x3,A.y,a31); a32=fmaf(x3,A.z,a32); a33=fmaf(x3,A.w,a33);
            a34=fmaf(x3,Bv.x,a34);a35=fmaf(x3,Bv.y,a35);a36=fmaf(x3,Bv.z,a36);a37=fmaf(x3,Bv.w,a37);
            bp += XSTRIDE;
        }

        // row norms (over ALL 256 cols): 4 squared sums, then ONE interleaved
        // butterfly reduce (4 independent chains per stage -> latency hidden)
        float n0 = a00*a00+a01*a01+a02*a02+a03*a03+a04*a04+a05*a05+a06*a06+a07*a07;
        float n1 = a10*a10+a11*a11+a12*a12+a13*a13+a14*a14+a15*a15+a16*a16+a17*a17;
        float n2 = a20*a20+a21*a21+a22*a22+a23*a23+a24*a24+a25*a25+a26*a26+a27*a27;
        float n3 = a30*a30+a31*a31+a32*a32+a33*a33+a34*a34+a35*a35+a36*a36+a37*a37;
        #pragma unroll
        for (int o = 16; o > 0; o >>= 1) {
            n0 += __shfl_xor_sync(0xffffffffu, n0, o);
            n1 += __shfl_xor_sync(0xffffffffu, n1, o);
            n2 += __shfl_xor_sync(0xffffffffu, n2, o);
            n3 += __shfl_xor_sync(0xffffffffu, n3, o);
        }
        const float inv0 = 1.0f / fmaxf(sqrtf(n0), 1e-12f);
        const float inv1 = 1.0f / fmaxf(sqrtf(n1), 1e-12f);
        const float inv2 = 1.0f / fmaxf(sqrtf(n2), 1e-12f);
        const float inv3 = 1.0f / fmaxf(sqrtf(n3), 1e-12f);

        float* rb0 = srow + (w << 2) * S;
        *(float4*)(rb0 + 0*S + 4*l)       = make_float4(a00*inv0, a01*inv0, a02*inv0, a03*inv0);
        *(float4*)(rb0 + 0*S + 128 + 4*l) = make_float4(a04*inv0, a05*inv0, a06*inv0, a07*inv0);
        *(float4*)(rb0 + 1*S + 4*l)       = make_float4(a10*inv1, a11*inv1, a12*inv1, a13*inv1);
        *(float4*)(rb0 + 1*S + 128 + 4*l) = make_float4(a14*inv1, a15*inv1, a16*inv1, a17*inv1);
        *(float4*)(rb0 + 2*S + 4*l)       = make_float4(a20*inv2, a21*inv2, a22*inv2, a23*inv2);
        *(float4*)(rb0 + 2*S + 128 + 4*l) = make_float4(a24*inv2, a25*inv2, a26*inv2, a27*inv2);
        *(float4*)(rb0 + 3*S + 4*l)       = make_float4(a30*inv3, a31*inv3, a32*inv3, a33*inv3);
        *(float4*)(rb0 + 3*S + 128 + 4*l) = make_float4(a34*inv3, a35*inv3, a36*inv3, a37*inv3);
        __syncwarp();

        // refresh warp-wide threshold once per pass
        {
            ull t2 = wmax64(best[0]);
            warpThr = (t2 > warpThr) ? t2 : warpThr;
            gate = (warpThr > best[0]) ? warpThr : best[0];
            gateF = fmaxf(keyval(gate), LOGIT_THR);
        }

        // ---- MLP (logit space) + gated top-k over this warp's 4 rows ----
        float c1[16], c2[16], cw2[16];
        #pragma unroll
        for (int k = 0; k < 16; k++) {
            c1[k]  = s_wt[k];
            c2[k]  = s_wt[16 + k];
            cw2[k] = s_wt[64 + k];
        }
        const float b2v = s_wt[80];

        #pragma unroll
        for (int qq = 0; qq < 4; qq++) {
            const int i = rbase0 + qq;
            const float* rb = rb0 + qq * S;
            const float twi = s_tw[i];
            const float wvi = s_iw[i];
            float rbase[16];
            #pragma unroll
            for (int k = 0; k < 16; k++)
                rbase[k] = fmaf(s_wt[32 + k], wvi, s_wt[48 + k]);   // a3*iw + b1

            const int flatbase = i << 8;
            int j = i + 1 + l;
            if (j < S) {
                // software pipeline: preload next point's data before the MLP body
                float sCur  = rb[j];
                float twCur = s_tw[j];
                for (; j < S; j += 32) {
                    const int jn = j + 32;
                    float sNext = 0.f, twNext = 0.f;
                    if (jn < S) { sNext = rb[jn]; twNext = s_tw[jn]; }
                    float t = twi * twCur;
                    float acc = b2v;
                    #pragma unroll
                    for (int k = 0; k < 16; k++) {
                        float pre = fmaf(c1[k], sCur, fmaf(c2[k], t, rbase[k]));
                        acc = fmaf(fmaxf(pre, 0.0f), cw2[k], acc);
                    }
                    // single float gate (covers threshold + current admission bound)
                    if (acc >= gateF) {
                        ull key = ((ull)f2ord(acc) << 32)
                                | (ull)(0xffffffffu - (unsigned)(flatbase + j));
                        if (key > gate) {
                            best[0] = key;
                            #pragma unroll
                            for (int n = 0; n < KNB - 1; n++) {
                                ull x = best[n], y = best[n + 1];
                                ull lo = (x < y) ? x : y;
                                ull hi = (x < y) ? y : x;
                                best[n] = lo; best[n + 1] = hi;
                            }
                            gate = (warpThr > best[0]) ? warpThr : best[0];
                            gateF = fmaxf(keyval(gate), LOGIT_THR);
                        }
                    }
                    sCur = sNext; twCur = twNext;
                }
            }
        }
        __syncwarp();
    }

    // ---- hierarchical merge: dump sorted lists -> warp top-20 -> CTA top-20 ----
    __syncthreads();                       // all warps done with Xs/srow
    ull* dump = (ull*)sm;                  // 256*20 ull = 40KB (inside Xs region)
    #pragma unroll
    for (int n = 0; n < KNB; n++) dump[tid * KNB + n] = best[n];
    __syncthreads();

    ull* wtop = (ull*)(sm + SROW_OFF);     // 8*20 ull
    {
        const ull* ml = dump + tid * KNB;  // own sorted-ascending list
        int p = KNB - 1;
        ull cand = ml[p];
        for (int r = 0; r < KNB; r++) {
            ull mm = wmax64(cand);
            if (cand == mm && mm != 0ull) { p--; cand = (p >= 0) ? ml[p] : 0ull; }
            if (l == 0) wtop[w * KNB + r] = mm;    // descending
        }
    }
    __syncthreads();

    if (w == 0) {
        float* oSrc = out;
        float* oDst = out + S * KNB;        // 5120
        float* oW   = out + 2 * S * KNB;    // 10240
        int p = 0;
        ull cand = (l < NWARPS) ? wtop[l * KNB] : 0ull;
        for (int r = 0; r < KNB; r++) {
            ull mm = wmax64(cand);
            if (l < NWARPS && cand == mm && mm != 0ull) {
                p++;
                cand = (p < KNB) ? wtop[l * KNB + p] : 0ull;
            }
            if (l == 0) {
                int slot = b * KNB + r;
                if (mm != 0ull) {
                    float acc = keyval(mm);
                    float val = __fdividef(1.0f, 1.0f + __expf(-acc));   // sigmoid (20/batch)
                    unsigned flat = 0xffffffffu - (unsigned)(mm & 0xffffffffu);
                    int ii = flat >> 8, jj = flat & 255;
                    oSrc[slot] = (float)(b * S + ii);
                    oDst[slot] = (float)(b * S + jj);
                    oW[slot]   = val;
                } else {
                    oSrc[slot] = 0.0f; oDst[slot] = 0.0f; oW[slot] = 0.0f;
                }
            }
        }
    }
}

extern "C" void kernel_launch(void* const* d_in, const int* in_sizes, int n_in,
                              void* d_out, int out_size)
{
    // metadata order: user_embeddings(unused), item_embeddings, timestamps,
    // interaction_weights, W1, b1, W2, b2, k_neighbors(=20, hardcoded)
    const float* item = (const float*)d_in[1];
    const float* tsg  = (const float*)d_in[2];
    const float* iwg  = (const float*)d_in[3];
    const float* W1   = (const float*)d_in[4];
    const float* b1   = (const float*)d_in[5];
    const float* W2   = (const float*)d_in[6];
    const float* b2   = (const float*)d_in[7];
    float* out = (float*)d_out;

    cudaFuncSetAttribute(ugc_kernel, cudaFuncAttributeMaxDynamicSharedMemorySize, SMEM_BYTES);
    ugc_kernel<<<S, NTHREADS, SMEM_BYTES>>>(item, tsg, iwg, W1, b1, W2, b2, out);
}

// round 15
// speedup vs baseline: 1.0346x; 1.0346x over previous
#include <cuda_runtime.h>
#include <cstdint>

#define S 256
#define E 64
#define KNB 20
#define NTHREADS 256
#define NWARPS 8
#define XSTRIDE 260   // padded row stride for Xs (16B-aligned, breaks STS conflicts)

// logit(0.1): sigmoid(acc) > 0.1  <=>  acc > LOGIT_THR
#define LOGIT_THR (-2.1972245773362196f)

// shared memory layout (in floats)
#define XS_OFF   0        // 64*260 = 16640: Xs[e][j], e-major stride 260 (reused as key dump)
#define SROW_OFF 16640    // 8192: per-warp 4 normalized-sims row buffers (reused as wtop)
#define TW_OFF   24832    // 256
#define IW_OFF   25088    // 256
#define RED_OFF  25344    // 64 (8B aligned) reduction scratch
#define WT_OFF   25408    // 96: a1,a2,a3,b1,w2,b2
#define SMEM_FLOATS 25504
#define SMEM_BYTES (SMEM_FLOATS * 4)

typedef unsigned long long ull;

// order-preserving uint32 of a float (handles negatives)
__device__ __forceinline__ unsigned f2ord(float f) {
    unsigned u = __float_as_uint(f);
    return u ^ ((u & 0x80000000u) ? 0xffffffffu : 0x80000000u);
}

// value (float) encoded in the high word of a key; -big for empty key
__device__ __forceinline__ float keyval(ull g) {
    if (g == 0ull) return -3.0e38f;
    unsigned u = (unsigned)(g >> 32);
    unsigned bits = (u & 0x80000000u) ? (u ^ 0x80000000u) : ~u;   // inverse f2ord
    return __uint_as_float(bits);
}

__device__ __forceinline__ ull wmax64(ull v) {
    #pragma unroll
    for (int o = 16; o > 0; o >>= 1) {
        ull t = __shfl_xor_sync(0xffffffffu, v, o);
        v = (t > v) ? t : v;
    }
    return v;
}

__global__ __launch_bounds__(NTHREADS, 2)
void ugc_kernel(const float* __restrict__ item,
                const float* __restrict__ tsg,
                const float* __restrict__ iwg,
                const float* __restrict__ gW1,
                const float* __restrict__ gb1,
                const float* __restrict__ gW2,
                const float* __restrict__ gb2,
                float* __restrict__ out)
{
    extern __shared__ float sm[];
    float* Xs    = sm + XS_OFF;
    float* srow  = sm + SROW_OFF;
    float* s_tw  = sm + TW_OFF;
    float* s_iw  = sm + IW_OFF;
    float* s_red = sm + RED_OFF;
    float* s_wt  = sm + WT_OFF;

    const int b   = blockIdx.x;
    const int tid = threadIdx.x;
    const int w   = tid >> 5;
    const int l   = tid & 31;

    // ---- stage MLP weights into smem (tiny) ----
    if (tid < 16) {
        s_wt[tid]      = gW1[tid];        // a1
        s_wt[16 + tid] = gW1[16 + tid];   // a2
        s_wt[32 + tid] = gW1[32 + tid];   // a3
        s_wt[48 + tid] = gb1[tid];        // b1
        s_wt[64 + tid] = gW2[tid];        // w2
    }
    if (tid == 0) s_wt[80] = gb2[0];

    // ---- timestamps max -> temporal weights; interaction weights ----
    const float tsv = tsg[b * S + tid];
    float v = tsv;
    #pragma unroll
    for (int o = 16; o > 0; o >>= 1) v = fmaxf(v, __shfl_xor_sync(0xffffffffu, v, o));
    if (l == 0) s_red[w] = v;
    __syncthreads();
    float tmax = s_red[0];
    #pragma unroll
    for (int r = 1; r < NWARPS; r++) tmax = fmaxf(tmax, s_red[r]);
    const float LN095 = -0.05129329438755058f;      // ln(0.95)
    s_tw[tid] = __expf(LN095 * (tmax - tsv));       // 0.95^(tmax - ts)
    s_iw[tid] = iwg[b * S + tid];

    // ---- stage X transposed into SMEM via coalesced 4x4 block transpose ----
    // Xs[e*XSTRIDE + j] = X[j][e]
    {
        const float* Xg = item + (size_t)b * (S * E);
        #pragma unroll
        for (int it = 0; it < 4; it++) {
            int blk = it * NTHREADS + tid;      // 0..1023 blocks of 4x4
            int eb  = blk & 15;                 // e-block (16 per row group)
            int jb  = blk >> 4;                 // j-block (64)
            float4 r0 = *(const float4*)(Xg + (4 * jb + 0) * E + 4 * eb);
            float4 r1 = *(const float4*)(Xg + (4 * jb + 1) * E + 4 * eb);
            float4 r2 = *(const float4*)(Xg + (4 * jb + 2) * E + 4 * eb);
            float4 r3 = *(const float4*)(Xg + (4 * jb + 3) * E + 4 * eb);
            *(float4*)(Xs + (4 * eb + 0) * XSTRIDE + 4 * jb) = make_float4(r0.x, r1.x, r2.x, r3.x);
            *(float4*)(Xs + (4 * eb + 1) * XSTRIDE + 4 * jb) = make_float4(r0.y, r1.y, r2.y, r3.y);
            *(float4*)(Xs + (4 * eb + 2) * XSTRIDE + 4 * jb) = make_float4(r0.z, r1.z, r2.z, r3.z);
            *(float4*)(Xs + (4 * eb + 3) * XSTRIDE + 4 * jb) = make_float4(r0.w, r1.w, r2.w, r3.w);
        }
    }
    __syncthreads();

    // ---- per-thread top-K (sorted ascending register list of packed keys) ----
    ull best[KNB];
    #pragma unroll
    for (int n = 0; n < KNB; n++) best[n] = 0ull;
    ull  warpThr = 0ull;        // warp-wide valid discard bound
    ull  gate    = 0ull;        // max(warpThr, best[0])
    float gateF  = LOGIT_THR;   // single-compare gate (subsumes edge threshold)

    // ---- main loop: 8 passes; warp owns adjacent row block {4m..4m+3},
    //      m = 8*pass + (pass odd ? 7-w : w)  -> exactly 4080 MLP points per warp ----
    for (int pass = 0; pass < 8; pass++) {
        const int m  = 8 * pass + ((pass & 1) ? (7 - w) : w);   // 0..63
        const int rbase0 = 4 * m;

        // 4x256 gram block: 32 accumulators; ONE LDS.128 broadcast serves 4 rows
        float a00=0,a01=0,a02=0,a03=0,a04=0,a05=0,a06=0,a07=0;
        float a10=0,a11=0,a12=0,a13=0,a14=0,a15=0,a16=0,a17=0;
        float a20=0,a21=0,a22=0,a23=0,a24=0,a25=0,a26=0,a27=0;
        float a30=0,a31=0,a32=0,a33=0,a34=0,a35=0,a36=0,a37=0;

        const float* bp = Xs;
        #pragma unroll 8
        for (int e = 0; e < E; e++) {
            float4 A  = *(const float4*)(bp + 4 * l);
            float4 Bv = *(const float4*)(bp + 128 + 4 * l);
            float4 X4 = *(const float4*)(bp + rbase0);      // broadcast: rows 4m..4m+3
            float x0 = X4.x, x1 = X4.y, x2 = X4.z, x3 = X4.w;
            a00=fmaf(x0,A.x,a00); a01=fmaf(x0,A.y,a01); a02=fmaf(x0,A.z,a02); a03=fmaf(x0,A.w,a03);
            a04=fmaf(x0,Bv.x,a04);a05=fmaf(x0,Bv.y,a05);a06=fmaf(x0,Bv.z,a06);a07=fmaf(x0,Bv.w,a07);
            a10=fmaf(x1,A.x,a10); a11=fmaf(x1,A.y,a11); a12=fmaf(x1,A.z,a12); a13=fmaf(x1,A.w,a13);
            a14=fmaf(x1,Bv.x,a14);a15=fmaf(x1,Bv.y,a15);a16=fmaf(x1,Bv.z,a16);a17=fmaf(x1,Bv.w,a17);
            a20=fmaf(x2,A.x,a20); a21=fmaf(x2,A.y,a21); a22=fmaf(x2,A.z,a22); a23=fmaf(x2,A.w,a23);
            a24=fmaf(x2,Bv.x,a24);a25=fmaf(x2,Bv.y,a25);a26=fmaf(x2,Bv.z,a26);a27=fmaf(x2,Bv.w,a27);
            a30=fmaf(x3,A.x,a30); a31=fmaf(x3,A.y,a31); a32=fmaf(x3,A.z,a32); a33=fmaf(x3,A.w,a33);
            a34=fmaf(x3,Bv.x,a34);a35=fmaf(x3,Bv.y,a35);a36=fmaf(x3,Bv.z,a36);a37=fmaf(x3,Bv.w,a37);
            bp += XSTRIDE;
        }

        // row norms (over ALL 256 cols): 4 squared sums, then ONE interleaved
        // butterfly reduce (4 independent chains per stage -> latency hidden)
        float n0 = a00*a00+a01*a01+a02*a02+a03*a03+a04*a04+a05*a05+a06*a06+a07*a07;
        float n1 = a10*a10+a11*a11+a12*a12+a13*a13+a14*a14+a15*a15+a16*a16+a17*a17;
        float n2 = a20*a20+a21*a21+a22*a22+a23*a23+a24*a24+a25*a25+a26*a26+a27*a27;
        float n3 = a30*a30+a31*a31+a32*a32+a33*a33+a34*a34+a35*a35+a36*a36+a37*a37;
        #pragma unroll
        for (int o = 16; o > 0; o >>= 1) {
            n0 += __shfl_xor_sync(0xffffffffu, n0, o);
            n1 += __shfl_xor_sync(0xffffffffu, n1, o);
            n2 += __shfl_xor_sync(0xffffffffu, n2, o);
            n3 += __shfl_xor_sync(0xffffffffu, n3, o);
        }
        const float inv0 = 1.0f / fmaxf(sqrtf(n0), 1e-12f);
        const float inv1 = 1.0f / fmaxf(sqrtf(n1), 1e-12f);
        const float inv2 = 1.0f / fmaxf(sqrtf(n2), 1e-12f);
        const float inv3 = 1.0f / fmaxf(sqrtf(n3), 1e-12f);

        float* rb0 = srow + (w << 2) * S;
        *(float4*)(rb0 + 0*S + 4*l)       = make_float4(a00*inv0, a01*inv0, a02*inv0, a03*inv0);
        *(float4*)(rb0 + 0*S + 128 + 4*l) = make_float4(a04*inv0, a05*inv0, a06*inv0, a07*inv0);
        *(float4*)(rb0 + 1*S + 4*l)       = make_float4(a10*inv1, a11*inv1, a12*inv1, a13*inv1);
        *(float4*)(rb0 + 1*S + 128 + 4*l) = make_float4(a14*inv1, a15*inv1, a16*inv1, a17*inv1);
        *(float4*)(rb0 + 2*S + 4*l)       = make_float4(a20*inv2, a21*inv2, a22*inv2, a23*inv2);
        *(float4*)(rb0 + 2*S + 128 + 4*l) = make_float4(a24*inv2, a25*inv2, a26*inv2, a27*inv2);
        *(float4*)(rb0 + 3*S + 4*l)       = make_float4(a30*inv3, a31*inv3, a32*inv3, a33*inv3);
        *(float4*)(rb0 + 3*S + 128 + 4*l) = make_float4(a34*inv3, a35*inv3, a36*inv3, a37*inv3);
        __syncwarp();

        // refresh warp-wide threshold once per pass
        {
            ull t2 = wmax64(best[0]);
            warpThr = (t2 > warpThr) ? t2 : warpThr;
            gate = (warpThr > best[0]) ? warpThr : best[0];
            gateF = fmaxf(keyval(gate), LOGIT_THR);
        }

        // ---- MLP (logit space) + gated top-k over this warp's 4 rows ----
        float c1[16], c2[16], cw2[16];
        #pragma unroll
        for (int k = 0; k < 16; k++) {
            c1[k]  = s_wt[k];
            c2[k]  = s_wt[16 + k];
            cw2[k] = s_wt[64 + k];
        }
        const float b2v = s_wt[80];

        #pragma unroll
        for (int qq = 0; qq < 4; qq++) {
            const int i = rbase0 + qq;
            const float* rb = rb0 + qq * S;
            const float twi = s_tw[i];
            const float wvi = s_iw[i];
            float rbase[16];
            #pragma unroll
            for (int k = 0; k < 16; k++)
                rbase[k] = fmaf(s_wt[32 + k], wvi, s_wt[48 + k]);   // a3*iw + b1

            const int flatbase = i << 8;
            for (int j = i + 1 + l; j < S; j += 32) {
                float s = rb[j];
                float t = twi * s_tw[j];
                float acc = b2v;
                #pragma unroll
                for (int k = 0; k < 16; k++) {
                    float pre = fmaf(c1[k], s, fmaf(c2[k], t, rbase[k]));
                    acc = fmaf(fmaxf(pre, 0.0f), cw2[k], acc);
                }
                // single float gate (covers threshold + current admission bound)
                if (acc >= gateF) {
                    ull key = ((ull)f2ord(acc) << 32)
                            | (ull)(0xffffffffu - (unsigned)(flatbase + j));
                    if (key > gate) {
                        best[0] = key;
                        #pragma unroll
                        for (int n = 0; n < KNB - 1; n++) {
                            ull x = best[n], y = best[n + 1];
                            ull lo = (x < y) ? x : y;
                            ull hi = (x < y) ? y : x;
                            best[n] = lo; best[n + 1] = hi;
                        }
                        gate = (warpThr > best[0]) ? warpThr : best[0];
                        gateF = fmaxf(keyval(gate), LOGIT_THR);
                    }
                }
            }
        }
        __syncwarp();
    }

    // ---- hierarchical merge: dump sorted lists -> warp top-20 -> CTA top-20 ----
    __syncthreads();                       // all warps done with Xs/srow
    ull* dump = (ull*)sm;                  // 256*20 ull = 40KB (inside Xs region)
    #pragma unroll
    for (int n = 0; n < KNB; n++) dump[tid * KNB + n] = best[n];
    __syncthreads();

    ull* wtop = (ull*)(sm + SROW_OFF);     // 8*20 ull
    {
        const ull* ml = dump + tid * KNB;  // own sorted-ascending list
        int p = KNB - 1;
        ull cand = ml[p];
        for (int r = 0; r < KNB; r++) {
            ull mm = wmax64(cand);
            if (cand == mm && mm != 0ull) { p--; cand = (p >= 0) ? ml[p] : 0ull; }
            if (l == 0) wtop[w * KNB + r] = mm;    // descending
        }
    }
    __syncthreads();

    if (w == 0) {
        float* oSrc = out;
        float* oDst = out + S * KNB;        // 5120
        float* oW   = out + 2 * S * KNB;    // 10240
        int p = 0;
        ull cand = (l < NWARPS) ? wtop[l * KNB] : 0ull;
        for (int r = 0; r < KNB; r++) {
            ull mm = wmax64(cand);
            if (l < NWARPS && cand == mm && mm != 0ull) {
                p++;
                cand = (p < KNB) ? wtop[l * KNB + p] : 0ull;
            }
            if (l == 0) {
                int slot = b * KNB + r;
                if (mm != 0ull) {
                    float acc = keyval(mm);
                    float val = __fdividef(1.0f, 1.0f + __expf(-acc));   // sigmoid (20/batch)
                    unsigned flat = 0xffffffffu - (unsigned)(mm & 0xffffffffu);
                    int ii = flat >> 8, jj = flat & 255;
                    oSrc[slot] = (float)(b * S + ii);
                    oDst[slot] = (float)(b * S + jj);
                    oW[slot]   = val;
                } else {
                    oSrc[slot] = 0.0f; oDst[slot] = 0.0f; oW[slot] = 0.0f;
                }
            }
        }
    }
}

extern "C" void kernel_launch(void* const* d_in, const int* in_sizes, int n_in,
                              void* d_out, int out_size)
{
    // metadata order: user_embeddings(unused), item_embeddings, timestamps,
    // interaction_weights, W1, b1, W2, b2, k_neighbors(=20, hardcoded)
    const float* item = (const float*)d_in[1];
    const float* tsg  = (const float*)d_in[2];
    const float* iwg  = (const float*)d_in[3];
    const float* W1   = (const float*)d_in[4];
    const float* b1   = (const float*)d_in[5];
    const float* W2   = (const float*)d_in[6];
    const float* b2   = (const float*)d_in[7];
    float* out = (float*)d_out;

    cudaFuncSetAttribute(ugc_kernel, cudaFuncAttributeMaxDynamicSharedMemorySize, SMEM_BYTES);
    ugc_kernel<<<S, NTHREADS, SMEM_BYTES>>>(item, tsg, iwg, W1, b1, W2, b2, out);
}

// round 16
// speedup vs baseline: 1.0349x; 1.0004x over previous
#include <cuda_runtime.h>
#include <cstdint>

#define S 256
#define E 64
#define KNB 20
#define NTHREADS 256
#define NWARPS 8
#define XSTRIDE 260   // padded row stride for Xs (16B-aligned, breaks STS conflicts)

// logit(0.1): sigmoid(acc) > 0.1  <=>  acc > LOGIT_THR
#define LOGIT_THR (-2.1972245773362196f)

// shared memory layout (in floats)
#define XS_OFF   0        // 64*260 = 16640: Xs[e][j], e-major stride 260 (reused as key dump)
#define SROW_OFF 16640    // 8192: per-warp 4 normalized-sims row buffers (reused as wtop)
#define TW_OFF   24832    // 256
#define IW_OFF   25088    // 256
#define RED_OFF  25344    // 64 (8B aligned) reduction scratch
#define WT_OFF   25408    // 96: a1,a2,a3,b1,w2,b2
#define SMEM_FLOATS 25504
#define SMEM_BYTES (SMEM_FLOATS * 4)

typedef unsigned long long ull;

// order-preserving uint32 of a float (handles negatives)
__device__ __forceinline__ unsigned f2ord(float f) {
    unsigned u = __float_as_uint(f);
    return u ^ ((u & 0x80000000u) ? 0xffffffffu : 0x80000000u);
}

// value (float) encoded in the high word of a key; -big for empty key
__device__ __forceinline__ float keyval(ull g) {
    if (g == 0ull) return -3.0e38f;
    unsigned u = (unsigned)(g >> 32);
    unsigned bits = (u & 0x80000000u) ? (u ^ 0x80000000u) : ~u;   // inverse f2ord
    return __uint_as_float(bits);
}

__device__ __forceinline__ ull wmax64(ull v) {
    #pragma unroll
    for (int o = 16; o > 0; o >>= 1) {
        ull t = __shfl_xor_sync(0xffffffffu, v, o);
        v = (t > v) ? t : v;
    }
    return v;
}

__global__ __launch_bounds__(NTHREADS, 2)
void ugc_kernel(const float* __restrict__ item,
                const float* __restrict__ tsg,
                const float* __restrict__ iwg,
                const float* __restrict__ gW1,
                const float* __restrict__ gb1,
                const float* __restrict__ gW2,
                const float* __restrict__ gb2,
                float* __restrict__ out)
{
    extern __shared__ float sm[];
    float* Xs    = sm + XS_OFF;
    float* srow  = sm + SROW_OFF;
    float* s_tw  = sm + TW_OFF;
    float* s_iw  = sm + IW_OFF;
    float* s_red = sm + RED_OFF;
    float* s_wt  = sm + WT_OFF;

    const int b   = blockIdx.x;
    const int tid = threadIdx.x;
    const int w   = tid >> 5;
    const int l   = tid & 31;

    // ---- stage MLP weights into smem (tiny) ----
    if (tid < 16) {
        s_wt[tid]      = gW1[tid];        // a1
        s_wt[16 + tid] = gW1[16 + tid];   // a2
        s_wt[32 + tid] = gW1[32 + tid];   // a3
        s_wt[48 + tid] = gb1[tid];        // b1
        s_wt[64 + tid] = gW2[tid];        // w2
    }
    if (tid == 0) s_wt[80] = gb2[0];

    // ---- timestamps max -> temporal weights; interaction weights ----
    const float tsv = tsg[b * S + tid];
    float v = tsv;
    #pragma unroll
    for (int o = 16; o > 0; o >>= 1) v = fmaxf(v, __shfl_xor_sync(0xffffffffu, v, o));
    if (l == 0) s_red[w] = v;
    __syncthreads();
    float tmax = s_red[0];
    #pragma unroll
    for (int r = 1; r < NWARPS; r++) tmax = fmaxf(tmax, s_red[r]);
    const float LN095 = -0.05129329438755058f;      // ln(0.95)
    s_tw[tid] = __expf(LN095 * (tmax - tsv));       // 0.95^(tmax - ts)
    s_iw[tid] = iwg[b * S + tid];

    // ---- stage X transposed into SMEM via coalesced 4x4 block transpose ----
    // Xs[e*XSTRIDE + j] = X[j][e]
    {
        const float* Xg = item + (size_t)b * (S * E);
        #pragma unroll
        for (int it = 0; it < 4; it++) {
            int blk = it * NTHREADS + tid;      // 0..1023 blocks of 4x4
            int eb  = blk & 15;                 // e-block (16 per row group)
            int jb  = blk >> 4;                 // j-block (64)
            float4 r0 = *(const float4*)(Xg + (4 * jb + 0) * E + 4 * eb);
            float4 r1 = *(const float4*)(Xg + (4 * jb + 1) * E + 4 * eb);
            float4 r2 = *(const float4*)(Xg + (4 * jb + 2) * E + 4 * eb);
            float4 r3 = *(const float4*)(Xg + (4 * jb + 3) * E + 4 * eb);
            *(float4*)(Xs + (4 * eb + 0) * XSTRIDE + 4 * jb) = make_float4(r0.x, r1.x, r2.x, r3.x);
            *(float4*)(Xs + (4 * eb + 1) * XSTRIDE + 4 * jb) = make_float4(r0.y, r1.y, r2.y, r3.y);
            *(float4*)(Xs + (4 * eb + 2) * XSTRIDE + 4 * jb) = make_float4(r0.z, r1.z, r2.z, r3.z);
            *(float4*)(Xs + (4 * eb + 3) * XSTRIDE + 4 * jb) = make_float4(r0.w, r1.w, r2.w, r3.w);
        }
    }
    __syncthreads();

    // ---- per-thread top-K (sorted ascending register list of packed keys) ----
    ull best[KNB];
    #pragma unroll
    for (int n = 0; n < KNB; n++) best[n] = 0ull;
    ull  warpThr = 0ull;        // warp-wide valid discard bound
    ull  gate    = 0ull;        // max(warpThr, best[0])
    float gateF  = LOGIT_THR;   // single-compare gate (subsumes edge threshold)

    // ---- main loop: 8 passes; warp owns adjacent row block {4m..4m+3},
    //      m = 8*pass + (pass odd ? 7-w : w)  -> exactly 4080 MLP points per warp ----
    for (int pass = 0; pass < 8; pass++) {
        const int m  = 8 * pass + ((pass & 1) ? (7 - w) : w);   // 0..63
        const int rbase0 = 4 * m;

        // 4x256 gram block: 32 accumulators; ONE LDS.128 broadcast serves 4 rows
        float a00=0,a01=0,a02=0,a03=0,a04=0,a05=0,a06=0,a07=0;
        float a10=0,a11=0,a12=0,a13=0,a14=0,a15=0,a16=0,a17=0;
        float a20=0,a21=0,a22=0,a23=0,a24=0,a25=0,a26=0,a27=0;
        float a30=0,a31=0,a32=0,a33=0,a34=0,a35=0,a36=0,a37=0;

        const float* bp = Xs;
        #pragma unroll 8
        for (int e = 0; e < E; e++) {
            float4 A  = *(const float4*)(bp + 4 * l);
            float4 Bv = *(const float4*)(bp + 128 + 4 * l);
            float4 X4 = *(const float4*)(bp + rbase0);      // broadcast: rows 4m..4m+3
            float x0 = X4.x, x1 = X4.y, x2 = X4.z, x3 = X4.w;
            a00=fmaf(x0,A.x,a00); a01=fmaf(x0,A.y,a01); a02=fmaf(x0,A.z,a02); a03=fmaf(x0,A.w,a03);
            a04=fmaf(x0,Bv.x,a04);a05=fmaf(x0,Bv.y,a05);a06=fmaf(x0,Bv.z,a06);a07=fmaf(x0,Bv.w,a07);
            a10=fmaf(x1,A.x,a10); a11=fmaf(x1,A.y,a11); a12=fmaf(x1,A.z,a12); a13=fmaf(x1,A.w,a13);
            a14=fmaf(x1,Bv.x,a14);a15=fmaf(x1,Bv.y,a15);a16=fmaf(x1,Bv.z,a16);a17=fmaf(x1,Bv.w,a17);
            a20=fmaf(x2,A.x,a20); a21=fmaf(x2,A.y,a21); a22=fmaf(x2,A.z,a22); a23=fmaf(x2,A.w,a23);
            a24=fmaf(x2,Bv.x,a24);a25=fmaf(x2,Bv.y,a25);a26=fmaf(x2,Bv.z,a26);a27=fmaf(x2,Bv.w,a27);
            a30=fmaf(x3,A.x,a30); a31=fmaf(x3,A.y,a31); a32=fmaf(x3,A.z,a32); a33=fmaf(x3,A.w,a33);
            a34=fmaf(x3,Bv.x,a34);a35=fmaf(x3,Bv.y,a35);a36=fmaf(x3,Bv.z,a36);a37=fmaf(x3,Bv.w,a37);
            bp += XSTRIDE;
        }

        // row norms (over ALL 256 cols): 4 squared sums, then ONE interleaved
        // butterfly reduce (4 independent chains per stage -> latency hidden)
        float n0 = a00*a00+a01*a01+a02*a02+a03*a03+a04*a04+a05*a05+a06*a06+a07*a07;
        float n1 = a10*a10+a11*a11+a12*a12+a13*a13+a14*a14+a15*a15+a16*a16+a17*a17;
        float n2 = a20*a20+a21*a21+a22*a22+a23*a23+a24*a24+a25*a25+a26*a26+a27*a27;
        float n3 = a30*a30+a31*a31+a32*a32+a33*a33+a34*a34+a35*a35+a36*a36+a37*a37;
        #pragma unroll
        for (int o = 16; o > 0; o >>= 1) {
            n0 += __shfl_xor_sync(0xffffffffu, n0, o);
            n1 += __shfl_xor_sync(0xffffffffu, n1, o);
            n2 += __shfl_xor_sync(0xffffffffu, n2, o);
            n3 += __shfl_xor_sync(0xffffffffu, n3, o);
        }
        const float inv0 = 1.0f / fmaxf(sqrtf(n0), 1e-12f);
        const float inv1 = 1.0f / fmaxf(sqrtf(n1), 1e-12f);
        const float inv2 = 1.0f / fmaxf(sqrtf(n2), 1e-12f);
        const float inv3 = 1.0f / fmaxf(sqrtf(n3), 1e-12f);

        float* rb0 = srow + (w << 2) * S;
        *(float4*)(rb0 + 0*S + 4*l)       = make_float4(a00*inv0, a01*inv0, a02*inv0, a03*inv0);
        *(float4*)(rb0 + 0*S + 128 + 4*l) = make_float4(a04*inv0, a05*inv0, a06*inv0, a07*inv0);
        *(float4*)(rb0 + 1*S + 4*l)       = make_float4(a10*inv1, a11*inv1, a12*inv1, a13*inv1);
        *(float4*)(rb0 + 1*S + 128 + 4*l) = make_float4(a14*inv1, a15*inv1, a16*inv1, a17*inv1);
        *(float4*)(rb0 + 2*S + 4*l)       = make_float4(a20*inv2, a21*inv2, a22*inv2, a23*inv2);
        *(float4*)(rb0 + 2*S + 128 + 4*l) = make_float4(a24*inv2, a25*inv2, a26*inv2, a27*inv2);
        *(float4*)(rb0 + 3*S + 4*l)       = make_float4(a30*inv3, a31*inv3, a32*inv3, a33*inv3);
        *(float4*)(rb0 + 3*S + 128 + 4*l) = make_float4(a34*inv3, a35*inv3, a36*inv3, a37*inv3);
        __syncwarp();

        // refresh warp-wide threshold once per pass
        {
            ull t2 = wmax64(best[0]);
            warpThr = (t2 > warpThr) ? t2 : warpThr;
            gate = (warpThr > best[0]) ? warpThr : best[0];
            gateF = fmaxf(keyval(gate), LOGIT_THR);
        }

        // ---- MLP (logit space) + gated top-k over this warp's 4 rows ----
        float c1[16], c2[16], cw2[16];
        #pragma unroll
        for (int k = 0; k < 16; k++) {
            c1[k]  = s_wt[k];
            c2[k]  = s_wt[16 + k];
            cw2[k] = s_wt[64 + k];
        }
        const float b2v = s_wt[80];

        #pragma unroll
        for (int qq = 0; qq < 4; qq++) {
            const int i = rbase0 + qq;
            const float* rb = rb0 + qq * S;
            const float twi = s_tw[i];
            const float wvi = s_iw[i];
            float rbase[16];
            #pragma unroll
            for (int k = 0; k < 16; k++)
                rbase[k] = fmaf(s_wt[32 + k], wvi, s_wt[48 + k]);   // a3*iw + b1

            const int flatbase = i << 8;
            for (int j = i + 1 + l; j < S; j += 32) {
                float s = rb[j];
                float t = twi * s_tw[j];
                float acc = b2v;
                #pragma unroll
                for (int k = 0; k < 16; k++) {
                    float pre = fmaf(c1[k], s, fmaf(c2[k], t, rbase[k]));
                    acc = fmaf(fmaxf(pre, 0.0f), cw2[k], acc);
                }
                // single float gate (covers threshold + current admission bound)
                if (acc >= gateF) {
                    ull key = ((ull)f2ord(acc) << 32)
                            | (ull)(0xffffffffu - (unsigned)(flatbase + j));
                    if (key > gate) {
                        best[0] = key;
                        #pragma unroll
                        for (int n = 0; n < KNB - 1; n++) {
                            ull x = best[n], y = best[n + 1];
                            ull lo = (x < y) ? x : y;
                            ull hi = (x < y) ? y : x;
                            best[n] = lo; best[n + 1] = hi;
                        }
                        gate = (warpThr > best[0]) ? warpThr : best[0];
                        gateF = fmaxf(keyval(gate), LOGIT_THR);
                    }
                }
            }
        }
        __syncwarp();
    }

    // ---- hierarchical merge: dump sorted lists -> warp top-20 -> CTA top-20 ----
    __syncthreads();                       // all warps done with Xs/srow
    ull* dump = (ull*)sm;                  // 256*20 ull = 40KB (inside Xs region)
    #pragma unroll
    for (int n = 0; n < KNB; n++) dump[tid * KNB + n] = best[n];
    __syncthreads();

    ull* wtop = (ull*)(sm + SROW_OFF);     // 8*20 ull
    {
        const ull* ml = dump + tid * KNB;  // own sorted-ascending list
        int p = KNB - 1;
        ull cand = ml[p];
        for (int r = 0; r < KNB; r++) {
            ull mm = wmax64(cand);
            if (cand == mm && mm != 0ull) { p--; cand = (p >= 0) ? ml[p] : 0ull; }
            if (l == 0) wtop[w * KNB + r] = mm;    // descending
        }
    }
    __syncthreads();

    if (w == 0) {
        float* oSrc = out;
        float* oDst = out + S * KNB;        // 5120
        float* oW   = out + 2 * S * KNB;    // 10240
        int p = 0;
        ull cand = (l < NWARPS) ? wtop[l * KNB] : 0ull;
        for (int r = 0; r < KNB; r++) {
            ull mm = wmax64(cand);
            if (l < NWARPS && cand == mm && mm != 0ull) {
                p++;
                cand = (p < KNB) ? wtop[l * KNB + p] : 0ull;
            }
            if (l == 0) {
                int slot = b * KNB + r;
                if (mm != 0ull) {
                    float acc = keyval(mm);
                    float val = __fdividef(1.0f, 1.0f + __expf(-acc));   // sigmoid (20/batch)
                    unsigned flat = 0xffffffffu - (unsigned)(mm & 0xffffffffu);
                    int ii = flat >> 8, jj = flat & 255;
                    oSrc[slot] = (float)(b * S + ii);
                    oDst[slot] = (float)(b * S + jj);
                    oW[slot]   = val;
                } else {
                    oSrc[slot] = 0.0f; oDst[slot] = 0.0f; oW[slot] = 0.0f;
                }
            }
        }
    }
}

extern "C" void kernel_launch(void* const* d_in, const int* in_sizes, int n_in,
                              void* d_out, int out_size)
{
    // metadata order: user_embeddings(unused), item_embeddings, timestamps,
    // interaction_weights, W1, b1, W2, b2, k_neighbors(=20, hardcoded)
    const float* item = (const float*)d_in[1];
    const float* tsg  = (const float*)d_in[2];
    const float* iwg  = (const float*)d_in[3];
    const float* W1   = (const float*)d_in[4];
    const float* b1   = (const float*)d_in[5];
    const float* W2   = (const float*)d_in[6];
    const float* b2   = (const float*)d_in[7];
    float* out = (float*)d_out;

    cudaFuncSetAttribute(ugc_kernel, cudaFuncAttributeMaxDynamicSharedMemorySize, SMEM_BYTES);
    ugc_kernel<<<S, NTHREADS, SMEM_BYTES>>>(item, tsg, iwg, W1, b1, W2, b2, out);
}